// round 9
// baseline (speedup 1.0000x reference)
#include <cuda_runtime.h>
#include <cuda_fp16.h>
#include <cuda_bf16.h>

// GATConv heads=1, self loops. h = x@W; out[d] = bias + softmax-weighted sum of h[src].
// Round 9: R8 with ONE change: h stored/gathered as fp16 (12.8MB) — halves the
// L2-bound gather traffic in k_gat. Accumulation and everything else stays fp32.

#define IN_DIM   128
#define OUT_DIM  64
#define N_MAX    100000
#define E_MAX    1600000
#define NEG_SLOPE 0.2f
#define CAP_LOG  7
#define CAP      128   // slots per dst bucket; P(deg+1 > 128) ~ e^-100, impossible

// ---------------- device scratch ----------------
__device__ __align__(16) __half g_hh[(size_t)N_MAX * OUT_DIM];     // 12.8 MB fp16 messages
__device__ float g_as[N_MAX];
__device__ float g_ad[N_MAX];
__device__ int   g_cnt[N_MAX];                                     // bucket cursor (=deg+1 after fill)
__device__ int   g_srcbuf[(size_t)N_MAX * CAP];                    // 51.2 MB, bucket layout
__device__ __align__(16) int2 g_pair[(size_t)N_MAX * CAP];         // (src<<7 byte-off, ex bits)

// ---------------- K0: cursor=1, self loop pre-placed at slot 0 ----------------
__global__ void k_init(int N) {
    int i = blockIdx.x * blockDim.x + threadIdx.x;
    if (i < N) {
        g_srcbuf[(size_t)i << CAP_LOG] = i;
        g_cnt[i] = 1;
    }
}

// ---------------- fill buckets directly (no scan) ----------------
__global__ __launch_bounds__(256) void k_fill(const int* __restrict__ ei, int E) {
    int e = blockIdx.x * blockDim.x + threadIdx.x;
    if (e >= E) return;
    int src = ei[e];
    int dst = ei[E + e];
    int pos = atomicAdd(&g_cnt[dst], 1);
    if (pos < CAP) g_srcbuf[((size_t)dst << CAP_LOG) + pos] = src;
}

// ---------------- K1: h = x @ W  + fused logits; h stored fp16 ----------------
#define TR 64
#define GEMM_SMEM (IN_DIM * OUT_DIM * 4 + TR * 129 * 4)

__global__ __launch_bounds__(256) void k_gemm(const float* __restrict__ x,
                                              const float* __restrict__ W,
                                              const float* __restrict__ a_src,
                                              const float* __restrict__ a_dst, int N) {
    extern __shared__ float smem[];
    float* Ws = smem;
    float* Xs = smem + IN_DIM * OUT_DIM;
    __shared__ float sPs[4][TR];
    __shared__ float sPd[4][TR];

    int tid = threadIdx.x;
    int rowBase = blockIdx.x * TR;

    for (int i = tid; i < (IN_DIM * OUT_DIM) / 4; i += 256)
        ((float4*)Ws)[i] = ((const float4*)W)[i];

    for (int i = tid; i < (TR * IN_DIM) / 4; i += 256) {
        int r  = i >> 5;
        int kq = i & 31;
        int row = rowBase + r;
        float4 v = (row < N) ? ((const float4*)x)[(size_t)row * 32 + kq]
                             : make_float4(0.f, 0.f, 0.f, 0.f);
        float* p = &Xs[r * 129 + kq * 4];
        p[0] = v.x; p[1] = v.y; p[2] = v.z; p[3] = v.w;
    }
    __syncthreads();

    int w    = tid >> 5;
    int lane = tid & 31;
    int rl   = ((w & 1) << 5) + lane;
    int cg   = w >> 1;
    int cb   = cg << 4;

    unsigned long long acc[8];
#pragma unroll
    for (int j = 0; j < 8; j++) acc[j] = 0ULL;

    const ulonglong2* Ws2 = (const ulonglong2*)Ws;

#pragma unroll 8
    for (int k = 0; k < IN_DIM; k++) {
        float xv = Xs[rl * 129 + k];
        unsigned long long xp;
        asm("mov.b64 %0, {%1, %1};" : "=l"(xp) : "f"(xv));
        int base = k * 16 + (cb >> 2);
#pragma unroll
        for (int j = 0; j < 4; j++) {
            ulonglong2 ww = Ws2[base + j];
            asm("fma.rn.f32x2 %0, %1, %2, %0;" : "+l"(acc[2 * j])     : "l"(xp), "l"(ww.x));
            asm("fma.rn.f32x2 %0, %1, %2, %0;" : "+l"(acc[2 * j + 1]) : "l"(xp), "l"(ww.y));
        }
    }

    float tmp[16];
#pragma unroll
    for (int j = 0; j < 8; j++) {
        float lo, hi;
        asm("mov.b64 {%0, %1}, %2;" : "=f"(lo), "=f"(hi) : "l"(acc[j]));
        tmp[2 * j] = lo; tmp[2 * j + 1] = hi;
    }

    int row = rowBase + rl;
    if (row < N) {
        // pack 16 fp32 -> 8 half2 -> two 16B stores
        unsigned int u[8];
#pragma unroll
        for (int j = 0; j < 8; j++) {
            __half2 hh = __floats2half2_rn(tmp[2 * j], tmp[2 * j + 1]);
            u[j] = *(unsigned int*)&hh;
        }
        uint4* hp = (uint4*)(g_hh + (size_t)row * OUT_DIM + cb);
        hp[0] = make_uint4(u[0], u[1], u[2], u[3]);
        hp[1] = make_uint4(u[4], u[5], u[6], u[7]);
    }

    // fused attention logits (fp32 precision from registers)
    float ps = 0.f, pd = 0.f;
#pragma unroll
    for (int j = 0; j < 16; j++) {
        ps += tmp[j] * __ldg(&a_src[cb + j]);
        pd += tmp[j] * __ldg(&a_dst[cb + j]);
    }
    sPs[cg][rl] = ps;
    sPd[cg][rl] = pd;
    __syncthreads();
    if (tid < TR) {
        int r2 = rowBase + tid;
        if (r2 < N) {
            g_as[r2] = sPs[0][tid] + sPs[1][tid] + sPs[2][tid] + sPs[3][tid];
            g_ad[r2] = sPd[0][tid] + sPd[1][tid] + sPd[2][tid] + sPd[3][tid];
        }
    }
}

// ---------------- K3: warp-per-dst aggregation, fp16 gather ----------------
__global__ __launch_bounds__(256) void k_gat(const float* __restrict__ bias,
                                             float* __restrict__ out, int N) {
    int gw   = (blockIdx.x * blockDim.x + threadIdx.x) >> 5;
    int lane = threadIdx.x & 31;
    if (gw >= N) return;
    size_t start = (size_t)gw << CAP_LOG;
    int cnt   = g_cnt[gw];
    float ad  = g_ad[gw];

    // phase 1: Sigma exp, lane-parallel, coalesced bucket reads; pack (src<<7, ex)
    float psum = 0.0f;
    for (int base = 0; base < cnt; base += 32) {
        int i = base + lane;
        float ex = 0.0f;
        if (i < cnt) {
            int src = g_srcbuf[start + i];
            float v = g_as[src] + ad;
            v = (v > 0.0f) ? v : NEG_SLOPE * v;
            ex = __expf(v);
            g_pair[start + i] = make_int2(src << 7, __float_as_int(ex));  // byte offset of row
        }
        psum += ex;
    }
#pragma unroll
    for (int o = 16; o; o >>= 1) psum += __shfl_xor_sync(~0u, psum, o);
    float invS = __fdividef(1.0f, psum);

    // phase 2: one uniform LDG.64 (pair) + one 4B/lane fp16 gather per edge
    float2 acc = make_float2(0.0f, 0.0f);
    const char* hlane = ((const char*)g_hh) + lane * 4;   // lane baseline (half2 per lane)
    const int2* pp = g_pair + start;
#pragma unroll 4
    for (int e = 0; e < cnt; e++) {
        int2  p  = pp[e];                                 // broadcast: (src<<7, ex bits)
        float ex = __int_as_float(p.y);
        __half2 hv2 = *(const __half2*)(hlane + (size_t)(unsigned)p.x);
        float2 hv = __half22float2(hv2);
        acc.x += ex * hv.x;
        acc.y += ex * hv.y;
    }
    float2 bv = ((const float2*)bias)[lane];
    float2 r = make_float2(acc.x * invS + bv.x, acc.y * invS + bv.y);
    ((float2*)out)[(size_t)gw * 32 + lane] = r;
}

// ---------------- launcher: bucket build on stream 0, GEMM forked onto s2 ----------------
extern "C" void kernel_launch(void* const* d_in, const int* in_sizes, int n_in,
                              void* d_out, int out_size) {
    const float* x     = (const float*)d_in[0];
    const int*   ei    = (const int*)  d_in[1];
    const float* W     = (const float*)d_in[2];
    const float* a_src = (const float*)d_in[3];
    const float* a_dst = (const float*)d_in[4];
    const float* bias  = (const float*)d_in[5];
    float* out = (float*)d_out;

    int N = in_sizes[0] / IN_DIM;
    int E = in_sizes[1] / 2;

    static cudaStream_t s2;
    static cudaEvent_t evA, evB;
    static bool init_done = false;
    if (!init_done) {
        cudaFuncSetAttribute(k_gemm, cudaFuncAttributeMaxDynamicSharedMemorySize, GEMM_SMEM);
        cudaStreamCreateWithFlags(&s2, cudaStreamNonBlocking);
        cudaEventCreateWithFlags(&evA, cudaEventDisableTiming);
        cudaEventCreateWithFlags(&evB, cudaEventDisableTiming);
        init_done = true;
    }

    // fork: GEMM (+ fused logits) on s2
    cudaEventRecord(evA, 0);
    cudaStreamWaitEvent(s2, evA, 0);
    k_gemm<<<(N + TR - 1) / TR, 256, GEMM_SMEM, s2>>>(x, W, a_src, a_dst, N);

    // bucket build on stream 0 (no scan)
    k_init<<<(N + 255) / 256, 256>>>(N);
    k_fill<<<(E + 255) / 256, 256>>>(ei, E);

    // join: k_gat needs buckets + h/as/ad
    cudaEventRecord(evB, s2);
    cudaStreamWaitEvent(0, evB, 0);
    k_gat<<<(N * 32 + 255) / 256, 256>>>(bias, out, N);
}

// round 10
// speedup vs baseline: 1.3296x; 1.3296x over previous
#include <cuda_runtime.h>
#include <cuda_bf16.h>

// GATConv heads=1, self loops. h = x@W; out[d] = bias + softmax-weighted sum of h[src].
// Round 10: fp32 base (R7/R8) with ONE change in k_gat phase 2: 2 edges per iteration,
// half-warp per edge (float4 gathers), uniform int4 pair load. Serial chain halved.

#define IN_DIM   128
#define OUT_DIM  64
#define N_MAX    100000
#define E_MAX    1600000
#define NEG_SLOPE 0.2f
#define CAP_LOG  7
#define CAP      128   // slots per dst bucket; P(deg+1 > 128) ~ e^-100, impossible

// ---------------- device scratch ----------------
__device__ __align__(16) float g_h[(size_t)N_MAX * OUT_DIM];       // 25.6 MB fp32 messages
__device__ float g_as[N_MAX];
__device__ float g_ad[N_MAX];
__device__ int   g_cnt[N_MAX];                                     // bucket cursor (=deg+1 after fill)
__device__ int   g_srcbuf[(size_t)N_MAX * CAP];                    // bucket layout
__device__ __align__(16) int2 g_pair[(size_t)N_MAX * CAP];         // (src<<8 byte-off, ex bits)

// ---------------- K0: cursor=1, self loop pre-placed at slot 0 ----------------
__global__ void k_init(int N) {
    int i = blockIdx.x * blockDim.x + threadIdx.x;
    if (i < N) {
        g_srcbuf[(size_t)i << CAP_LOG] = i;
        g_cnt[i] = 1;
    }
}

// ---------------- fill buckets directly (no scan) ----------------
__global__ __launch_bounds__(256) void k_fill(const int* __restrict__ ei, int E) {
    int e = blockIdx.x * blockDim.x + threadIdx.x;
    if (e >= E) return;
    int src = ei[e];
    int dst = ei[E + e];
    int pos = atomicAdd(&g_cnt[dst], 1);
    if (pos < CAP) g_srcbuf[((size_t)dst << CAP_LOG) + pos] = src;
}

// ---------------- K1: h = x @ W  + fused attention-logit epilogue ----------------
#define TR 64
#define GEMM_SMEM (IN_DIM * OUT_DIM * 4 + TR * 129 * 4)

__global__ __launch_bounds__(256) void k_gemm(const float* __restrict__ x,
                                              const float* __restrict__ W,
                                              const float* __restrict__ a_src,
                                              const float* __restrict__ a_dst, int N) {
    extern __shared__ float smem[];
    float* Ws = smem;
    float* Xs = smem + IN_DIM * OUT_DIM;
    __shared__ float sPs[4][TR];
    __shared__ float sPd[4][TR];

    int tid = threadIdx.x;
    int rowBase = blockIdx.x * TR;

    for (int i = tid; i < (IN_DIM * OUT_DIM) / 4; i += 256)
        ((float4*)Ws)[i] = ((const float4*)W)[i];

    for (int i = tid; i < (TR * IN_DIM) / 4; i += 256) {
        int r  = i >> 5;
        int kq = i & 31;
        int row = rowBase + r;
        float4 v = (row < N) ? ((const float4*)x)[(size_t)row * 32 + kq]
                             : make_float4(0.f, 0.f, 0.f, 0.f);
        float* p = &Xs[r * 129 + kq * 4];
        p[0] = v.x; p[1] = v.y; p[2] = v.z; p[3] = v.w;
    }
    __syncthreads();

    int w    = tid >> 5;
    int lane = tid & 31;
    int rl   = ((w & 1) << 5) + lane;
    int cg   = w >> 1;
    int cb   = cg << 4;

    unsigned long long acc[8];
#pragma unroll
    for (int j = 0; j < 8; j++) acc[j] = 0ULL;

    const ulonglong2* Ws2 = (const ulonglong2*)Ws;

#pragma unroll 8
    for (int k = 0; k < IN_DIM; k++) {
        float xv = Xs[rl * 129 + k];
        unsigned long long xp;
        asm("mov.b64 %0, {%1, %1};" : "=l"(xp) : "f"(xv));
        int base = k * 16 + (cb >> 2);
#pragma unroll
        for (int j = 0; j < 4; j++) {
            ulonglong2 ww = Ws2[base + j];
            asm("fma.rn.f32x2 %0, %1, %2, %0;" : "+l"(acc[2 * j])     : "l"(xp), "l"(ww.x));
            asm("fma.rn.f32x2 %0, %1, %2, %0;" : "+l"(acc[2 * j + 1]) : "l"(xp), "l"(ww.y));
        }
    }

    float tmp[16];
#pragma unroll
    for (int j = 0; j < 8; j++) {
        float lo, hi;
        asm("mov.b64 {%0, %1}, %2;" : "=f"(lo), "=f"(hi) : "l"(acc[j]));
        tmp[2 * j] = lo; tmp[2 * j + 1] = hi;
    }

    int row = rowBase + rl;
    if (row < N) {
        float4* hp = (float4*)(g_h + (size_t)row * OUT_DIM + cb);
#pragma unroll
        for (int j = 0; j < 4; j++)
            hp[j] = make_float4(tmp[4 * j], tmp[4 * j + 1], tmp[4 * j + 2], tmp[4 * j + 3]);
    }

    // fused attention logits
    float ps = 0.f, pd = 0.f;
#pragma unroll
    for (int j = 0; j < 16; j++) {
        ps += tmp[j] * __ldg(&a_src[cb + j]);
        pd += tmp[j] * __ldg(&a_dst[cb + j]);
    }
    sPs[cg][rl] = ps;
    sPd[cg][rl] = pd;
    __syncthreads();
    if (tid < TR) {
        int r2 = rowBase + tid;
        if (r2 < N) {
            g_as[r2] = sPs[0][tid] + sPs[1][tid] + sPs[2][tid] + sPs[3][tid];
            g_ad[r2] = sPd[0][tid] + sPd[1][tid] + sPd[2][tid] + sPd[3][tid];
        }
    }
}

// ---------------- K3: warp-per-dst; phase 2 = 2 edges/iter, half-warp each ----------------
__global__ __launch_bounds__(256) void k_gat(const float* __restrict__ bias,
                                             float* __restrict__ out, int N) {
    int gw   = (blockIdx.x * blockDim.x + threadIdx.x) >> 5;
    int lane = threadIdx.x & 31;
    if (gw >= N) return;
    size_t start = (size_t)gw << CAP_LOG;
    int cnt   = g_cnt[gw];
    float ad  = g_ad[gw];

    // phase 1: Sigma exp, lane-parallel, coalesced bucket reads; pack (src<<8, ex)
    float psum = 0.0f;
    for (int base = 0; base < cnt; base += 32) {
        int i = base + lane;
        float ex = 0.0f;
        if (i < cnt) {
            int src = g_srcbuf[start + i];
            float v = g_as[src] + ad;
            v = (v > 0.0f) ? v : NEG_SLOPE * v;
            ex = __expf(v);
            g_pair[start + i] = make_int2(src << 8, __float_as_int(ex));  // byte offset of 256B row
        }
        psum += ex;
    }
#pragma unroll
    for (int o = 16; o; o >>= 1) psum += __shfl_xor_sync(~0u, psum, o);
    float invS = __fdividef(1.0f, psum);

    // phase 2: 2 edges per iteration. Lanes 0-15 take edge e, lanes 16-31 edge e+1.
    // One uniform int4 load covers both pairs. Each thread gathers float4 (16B) of
    // its edge's h row. Slot `cnt` (odd tail) is never written -> zeros -> ex=0, off=0: safe.
    int half = lane >> 4;        // 0 or 1
    int l16  = lane & 15;
    float4 acc = make_float4(0.f, 0.f, 0.f, 0.f);
    const char* hbase = (const char*)g_h + (l16 << 4);   // this thread's 16B column slice
    const int4* pq = (const int4*)(g_pair + start);      // 16B-aligned (bucket = 1KB aligned)

#pragma unroll 4
    for (int e2 = 0; e2 < ((cnt + 1) >> 1); e2++) {
        int4 p = pq[e2];                                  // (offA, exA, offB, exB) uniform
        int   off = half ? p.z : p.x;
        float ex  = __int_as_float(half ? p.w : p.y);
        float4 hv = *(const float4*)(hbase + (size_t)(unsigned)off);
        acc.x += ex * hv.x;
        acc.y += ex * hv.y;
        acc.z += ex * hv.z;
        acc.w += ex * hv.w;
    }

    // combine halves: lane i (<16) += lane i+16
    acc.x += __shfl_down_sync(~0u, acc.x, 16);
    acc.y += __shfl_down_sync(~0u, acc.y, 16);
    acc.z += __shfl_down_sync(~0u, acc.z, 16);
    acc.w += __shfl_down_sync(~0u, acc.w, 16);

    if (half == 0) {
        float4 bv = ((const float4*)bias)[l16];
        float4 r = make_float4(acc.x * invS + bv.x, acc.y * invS + bv.y,
                               acc.z * invS + bv.z, acc.w * invS + bv.w);
        ((float4*)out)[(size_t)gw * 16 + l16] = r;
    }
}

// ---------------- launcher: bucket build on stream 0, GEMM forked onto s2 ----------------
extern "C" void kernel_launch(void* const* d_in, const int* in_sizes, int n_in,
                              void* d_out, int out_size) {
    const float* x     = (const float*)d_in[0];
    const int*   ei    = (const int*)  d_in[1];
    const float* W     = (const float*)d_in[2];
    const float* a_src = (const float*)d_in[3];
    const float* a_dst = (const float*)d_in[4];
    const float* bias  = (const float*)d_in[5];
    float* out = (float*)d_out;

    int N = in_sizes[0] / IN_DIM;
    int E = in_sizes[1] / 2;

    static cudaStream_t s2;
    static cudaEvent_t evA, evB;
    static bool init_done = false;
    if (!init_done) {
        cudaFuncSetAttribute(k_gemm, cudaFuncAttributeMaxDynamicSharedMemorySize, GEMM_SMEM);
        cudaStreamCreateWithFlags(&s2, cudaStreamNonBlocking);
        cudaEventCreateWithFlags(&evA, cudaEventDisableTiming);
        cudaEventCreateWithFlags(&evB, cudaEventDisableTiming);
        init_done = true;
    }

    // fork: GEMM (+ fused logits) on s2
    cudaEventRecord(evA, 0);
    cudaStreamWaitEvent(s2, evA, 0);
    k_gemm<<<(N + TR - 1) / TR, 256, GEMM_SMEM, s2>>>(x, W, a_src, a_dst, N);

    // bucket build on stream 0 (no scan)
    k_init<<<(N + 255) / 256, 256>>>(N);
    k_fill<<<(E + 255) / 256, 256>>>(ei, E);

    // join: k_gat needs buckets + h/as/ad
    cudaEventRecord(evB, s2);
    cudaStreamWaitEvent(0, evB, 0);
    k_gat<<<(N * 32 + 255) / 256, 256>>>(bias, out, N);
}

// round 11
// speedup vs baseline: 1.4471x; 1.0883x over previous
#include <cuda_runtime.h>
#include <cuda_fp16.h>
#include <cuda_bf16.h>

// GATConv heads=1, self loops. h = x@W; out[d] = bias + softmax-weighted sum of h[src].
// Round 11: R10 half-warp k_gat structure + fp16 h (128B rows): 1 gather wavefront/edge
// instead of 2. Conversions amortized 2 per 4 values per thread. Accumulation fp32.

#define IN_DIM   128
#define OUT_DIM  64
#define N_MAX    100000
#define E_MAX    1600000
#define NEG_SLOPE 0.2f
#define CAP_LOG  7
#define CAP      128   // slots per dst bucket; P(deg+1 > 128) ~ e^-100, impossible

// ---------------- device scratch ----------------
__device__ __align__(16) __half g_hh[(size_t)N_MAX * OUT_DIM];     // 12.8 MB fp16 messages
__device__ float g_as[N_MAX];
__device__ float g_ad[N_MAX];
__device__ int   g_cnt[N_MAX];                                     // bucket cursor (=deg+1 after fill)
__device__ int   g_srcbuf[(size_t)N_MAX * CAP];                    // bucket layout
__device__ __align__(16) int2 g_pair[(size_t)N_MAX * CAP];         // (src<<7 byte-off, ex bits)

// ---------------- K0: cursor=1, self loop pre-placed at slot 0 ----------------
__global__ void k_init(int N) {
    int i = blockIdx.x * blockDim.x + threadIdx.x;
    if (i < N) {
        g_srcbuf[(size_t)i << CAP_LOG] = i;
        g_cnt[i] = 1;
    }
}

// ---------------- fill buckets directly (no scan) ----------------
__global__ __launch_bounds__(256) void k_fill(const int* __restrict__ ei, int E) {
    int e = blockIdx.x * blockDim.x + threadIdx.x;
    if (e >= E) return;
    int src = ei[e];
    int dst = ei[E + e];
    int pos = atomicAdd(&g_cnt[dst], 1);
    if (pos < CAP) g_srcbuf[((size_t)dst << CAP_LOG) + pos] = src;
}

// ---------------- K1: h = x @ W  + fused logits; h stored fp16 ----------------
#define TR 64
#define GEMM_SMEM (IN_DIM * OUT_DIM * 4 + TR * 129 * 4)

__global__ __launch_bounds__(256) void k_gemm(const float* __restrict__ x,
                                              const float* __restrict__ W,
                                              const float* __restrict__ a_src,
                                              const float* __restrict__ a_dst, int N) {
    extern __shared__ float smem[];
    float* Ws = smem;
    float* Xs = smem + IN_DIM * OUT_DIM;
    __shared__ float sPs[4][TR];
    __shared__ float sPd[4][TR];

    int tid = threadIdx.x;
    int rowBase = blockIdx.x * TR;

    for (int i = tid; i < (IN_DIM * OUT_DIM) / 4; i += 256)
        ((float4*)Ws)[i] = ((const float4*)W)[i];

    for (int i = tid; i < (TR * IN_DIM) / 4; i += 256) {
        int r  = i >> 5;
        int kq = i & 31;
        int row = rowBase + r;
        float4 v = (row < N) ? ((const float4*)x)[(size_t)row * 32 + kq]
                             : make_float4(0.f, 0.f, 0.f, 0.f);
        float* p = &Xs[r * 129 + kq * 4];
        p[0] = v.x; p[1] = v.y; p[2] = v.z; p[3] = v.w;
    }
    __syncthreads();

    int w    = tid >> 5;
    int lane = tid & 31;
    int rl   = ((w & 1) << 5) + lane;
    int cg   = w >> 1;
    int cb   = cg << 4;

    unsigned long long acc[8];
#pragma unroll
    for (int j = 0; j < 8; j++) acc[j] = 0ULL;

    const ulonglong2* Ws2 = (const ulonglong2*)Ws;

#pragma unroll 8
    for (int k = 0; k < IN_DIM; k++) {
        float xv = Xs[rl * 129 + k];
        unsigned long long xp;
        asm("mov.b64 %0, {%1, %1};" : "=l"(xp) : "f"(xv));
        int base = k * 16 + (cb >> 2);
#pragma unroll
        for (int j = 0; j < 4; j++) {
            ulonglong2 ww = Ws2[base + j];
            asm("fma.rn.f32x2 %0, %1, %2, %0;" : "+l"(acc[2 * j])     : "l"(xp), "l"(ww.x));
            asm("fma.rn.f32x2 %0, %1, %2, %0;" : "+l"(acc[2 * j + 1]) : "l"(xp), "l"(ww.y));
        }
    }

    float tmp[16];
#pragma unroll
    for (int j = 0; j < 8; j++) {
        float lo, hi;
        asm("mov.b64 {%0, %1}, %2;" : "=f"(lo), "=f"(hi) : "l"(acc[j]));
        tmp[2 * j] = lo; tmp[2 * j + 1] = hi;
    }

    int row = rowBase + rl;
    if (row < N) {
        // 16 fp32 -> 8 half2 -> two 16B stores
        unsigned int u[8];
#pragma unroll
        for (int j = 0; j < 8; j++) {
            __half2 hh = __floats2half2_rn(tmp[2 * j], tmp[2 * j + 1]);
            u[j] = *(unsigned int*)&hh;
        }
        uint4* hp = (uint4*)(g_hh + (size_t)row * OUT_DIM + cb);
        hp[0] = make_uint4(u[0], u[1], u[2], u[3]);
        hp[1] = make_uint4(u[4], u[5], u[6], u[7]);
    }

    // fused attention logits (fp32 precision from registers)
    float ps = 0.f, pd = 0.f;
#pragma unroll
    for (int j = 0; j < 16; j++) {
        ps += tmp[j] * __ldg(&a_src[cb + j]);
        pd += tmp[j] * __ldg(&a_dst[cb + j]);
    }
    sPs[cg][rl] = ps;
    sPd[cg][rl] = pd;
    __syncthreads();
    if (tid < TR) {
        int r2 = rowBase + tid;
        if (r2 < N) {
            g_as[r2] = sPs[0][tid] + sPs[1][tid] + sPs[2][tid] + sPs[3][tid];
            g_ad[r2] = sPd[0][tid] + sPd[1][tid] + sPd[2][tid] + sPd[3][tid];
        }
    }
}

// ---------------- K3: warp-per-dst; 2 edges/iter, half-warp each, fp16 gather ----------------
__global__ __launch_bounds__(256) void k_gat(const float* __restrict__ bias,
                                             float* __restrict__ out, int N) {
    int gw   = (blockIdx.x * blockDim.x + threadIdx.x) >> 5;
    int lane = threadIdx.x & 31;
    if (gw >= N) return;
    size_t start = (size_t)gw << CAP_LOG;
    int cnt   = g_cnt[gw];
    float ad  = g_ad[gw];

    // phase 1: Sigma exp, lane-parallel; pack (src<<7 byte-offset of 128B fp16 row, ex)
    float psum = 0.0f;
    for (int base = 0; base < cnt; base += 32) {
        int i = base + lane;
        float ex = 0.0f;
        if (i < cnt) {
            int src = g_srcbuf[start + i];
            float v = g_as[src] + ad;
            v = (v > 0.0f) ? v : NEG_SLOPE * v;
            ex = __expf(v);
            g_pair[start + i] = make_int2(src << 7, __float_as_int(ex));
        }
        psum += ex;
    }
#pragma unroll
    for (int o = 16; o; o >>= 1) psum += __shfl_xor_sync(~0u, psum, o);
    float invS = __fdividef(1.0f, psum);

    // phase 2: 2 edges/iter. Lanes 0-15 edge e, lanes 16-31 edge e+1. Uniform int4 pair
    // load; each thread gathers 8B (4 halves) of its edge's 128B row -> 1 wavefront/edge.
    // Odd-tail slot `cnt` never written (zero-init) -> ex=0, off=0: harmless.
    int half = lane >> 4;
    int l16  = lane & 15;
    float4 acc = make_float4(0.f, 0.f, 0.f, 0.f);
    const char* hbase = (const char*)g_hh + (l16 << 3);   // this thread's 8B slice
    const int4* pq = (const int4*)(g_pair + start);       // bucket 16B-aligned

#pragma unroll 4
    for (int e2 = 0; e2 < ((cnt + 1) >> 1); e2++) {
        int4 p = pq[e2];                                   // (offA, exA, offB, exB) uniform
        int   off = half ? p.z : p.x;
        float ex  = __int_as_float(half ? p.w : p.y);
        uint2 hv2 = *(const uint2*)(hbase + (size_t)(unsigned)off);
        float2 a = __half22float2(*(const __half2*)&hv2.x);
        float2 b = __half22float2(*(const __half2*)&hv2.y);
        acc.x += ex * a.x;
        acc.y += ex * a.y;
        acc.z += ex * b.x;
        acc.w += ex * b.y;
    }

    // combine halves: lane i (<16) += lane i+16
    acc.x += __shfl_down_sync(~0u, acc.x, 16);
    acc.y += __shfl_down_sync(~0u, acc.y, 16);
    acc.z += __shfl_down_sync(~0u, acc.z, 16);
    acc.w += __shfl_down_sync(~0u, acc.w, 16);

    if (half == 0) {
        float4 bv = ((const float4*)bias)[l16];
        float4 r = make_float4(acc.x * invS + bv.x, acc.y * invS + bv.y,
                               acc.z * invS + bv.z, acc.w * invS + bv.w);
        ((float4*)out)[(size_t)gw * 16 + l16] = r;
    }
}

// ---------------- launcher: bucket build on stream 0, GEMM forked onto s2 ----------------
extern "C" void kernel_launch(void* const* d_in, const int* in_sizes, int n_in,
                              void* d_out, int out_size) {
    const float* x     = (const float*)d_in[0];
    const int*   ei    = (const int*)  d_in[1];
    const float* W     = (const float*)d_in[2];
    const float* a_src = (const float*)d_in[3];
    const float* a_dst = (const float*)d_in[4];
    const float* bias  = (const float*)d_in[5];
    float* out = (float*)d_out;

    int N = in_sizes[0] / IN_DIM;
    int E = in_sizes[1] / 2;

    static cudaStream_t s2;
    static cudaEvent_t evA, evB;
    static bool init_done = false;
    if (!init_done) {
        cudaFuncSetAttribute(k_gemm, cudaFuncAttributeMaxDynamicSharedMemorySize, GEMM_SMEM);
        cudaStreamCreateWithFlags(&s2, cudaStreamNonBlocking);
        cudaEventCreateWithFlags(&evA, cudaEventDisableTiming);
        cudaEventCreateWithFlags(&evB, cudaEventDisableTiming);
        init_done = true;
    }

    // fork: GEMM (+ fused logits) on s2
    cudaEventRecord(evA, 0);
    cudaStreamWaitEvent(s2, evA, 0);
    k_gemm<<<(N + TR - 1) / TR, 256, GEMM_SMEM, s2>>>(x, W, a_src, a_dst, N);

    // bucket build on stream 0 (no scan)
    k_init<<<(N + 255) / 256, 256>>>(N);
    k_fill<<<(E + 255) / 256, 256>>>(ei, E);

    // join: k_gat needs buckets + h/as/ad
    cudaEventRecord(evB, s2);
    cudaStreamWaitEvent(0, evB, 0);
    k_gat<<<(N * 32 + 255) / 256, 256>>>(bias, out, N);
}